// round 1
// baseline (speedup 1.0000x reference)
#include <cuda_runtime.h>

#define B_   128
#define LQ_  512
#define LD_  512
#define DIM  128
#define TQ   64
#define TD   128
#define DPAD 132          // DIM + 4 floats pad -> 4-bank stride between rows
#define NTHREADS 256

__global__ void zero_out_kernel(float* out) {
    if (threadIdx.x < B_) out[threadIdx.x] = 0.0f;
}

__global__ __launch_bounds__(NTHREADS, 2)
void colbert_kernel(const float* __restrict__ Qg,
                    const float* __restrict__ Dg,
                    float* __restrict__ out) {
    extern __shared__ float smem[];
    float* Qs     = smem;                 // TQ * DPAD
    float* Ds     = Qs + TQ * DPAD;       // TD * DPAD
    float* dsq    = Ds + TD * DPAD;       // TD
    float* qsq    = dsq + TD;             // TQ
    float* blksum = qsq + TQ;             // 1

    const int b  = blockIdx.x >> 3;       // 8 q-tiles per batch
    const int qt = blockIdx.x & 7;
    const float* Qb = Qg + (b * LQ_ + qt * TQ) * DIM;
    const float* Db = Dg + b * LD_ * DIM;

    const int tid = threadIdx.x;
    const int tx  = tid & 15;             // doc direction
    const int ty  = tid >> 4;             // query direction

    // ---- load Q tile (coalesced float4, row-major padded) ----
    #pragma unroll
    for (int i = tid; i < TQ * (DIM / 4); i += NTHREADS) {
        int q = i >> 5, c = i & 31;
        float4 v = reinterpret_cast<const float4*>(Qb)[q * (DIM / 4) + c];
        *reinterpret_cast<float4*>(&Qs[q * DPAD + c * 4]) = v;
    }
    if (tid == 0) *blksum = 0.0f;
    __syncthreads();

    // ---- q row norms: 4 lanes per query row ----
    {
        int q = tid >> 2, p = tid & 3;
        float s = 0.0f;
        #pragma unroll
        for (int c = 0; c < 8; c++) {
            float4 v = *reinterpret_cast<const float4*>(&Qs[q * DPAD + (p * 8 + c) * 4]);
            s += v.x * v.x + v.y * v.y + v.z * v.z + v.w * v.w;
        }
        s += __shfl_xor_sync(0xffffffffu, s, 1);
        s += __shfl_xor_sync(0xffffffffu, s, 2);
        if (p == 0) qsq[q] = s;
    }

    float rmax[4];
    #pragma unroll
    for (int qi = 0; qi < 4; qi++) rmax[qi] = -3.402823e38f;

    for (int kt = 0; kt < LD_ / TD; kt++) {
        __syncthreads();   // protect Ds/dsq from previous iteration readers

        // ---- load doc tile ----
        #pragma unroll
        for (int i = tid; i < TD * (DIM / 4); i += NTHREADS) {
            int k = i >> 5, c = i & 31;
            float4 v = reinterpret_cast<const float4*>(Db)[(kt * TD + k) * (DIM / 4) + c];
            *reinterpret_cast<float4*>(&Ds[k * DPAD + c * 4]) = v;
        }
        __syncthreads();

        // ---- doc row norms: 2 lanes per doc row ----
        {
            int k = tid >> 1, p = tid & 1;
            float s = 0.0f;
            #pragma unroll
            for (int c = 0; c < 16; c++) {
                float4 v = *reinterpret_cast<const float4*>(&Ds[k * DPAD + (p * 16 + c) * 4]);
                s += v.x * v.x + v.y * v.y + v.z * v.z + v.w * v.w;
            }
            s += __shfl_xor_sync(0xffffffffu, s, 1);
            if (p == 0) dsq[k] = s;
        }
        __syncthreads();

        // ---- 64x128 tile of dot products, 4x8 per thread ----
        float acc[4][8];
        #pragma unroll
        for (int qi = 0; qi < 4; qi++)
            #pragma unroll
            for (int di = 0; di < 8; di++) acc[qi][di] = 0.0f;

        #pragma unroll 4
        for (int c = 0; c < DIM / 4; c++) {
            float4 qv[4], dv[8];
            #pragma unroll
            for (int qi = 0; qi < 4; qi++)
                qv[qi] = *reinterpret_cast<const float4*>(&Qs[(qi * 16 + ty) * DPAD + c * 4]);
            #pragma unroll
            for (int di = 0; di < 8; di++)
                dv[di] = *reinterpret_cast<const float4*>(&Ds[(di * 16 + tx) * DPAD + c * 4]);
            #pragma unroll
            for (int qi = 0; qi < 4; qi++)
                #pragma unroll
                for (int di = 0; di < 8; di++) {
                    float a = acc[qi][di];
                    a = fmaf(qv[qi].x, dv[di].x, a);
                    a = fmaf(qv[qi].y, dv[di].y, a);
                    a = fmaf(qv[qi].z, dv[di].z, a);
                    a = fmaf(qv[qi].w, dv[di].w, a);
                    acc[qi][di] = a;
                }
        }

        // ---- fused epilogue: neg_dist = 2*qd - dsq ; running max ----
        #pragma unroll
        for (int di = 0; di < 8; di++) {
            float ds = dsq[di * 16 + tx];
            #pragma unroll
            for (int qi = 0; qi < 4; qi++) {
                float nd = fmaf(2.0f, acc[qi][di], -ds);
                rmax[qi] = fmaxf(rmax[qi], nd);
            }
        }
    }

    // ---- reduce max across the 16 tx lanes (stays inside 16-lane groups) ----
    #pragma unroll
    for (int qi = 0; qi < 4; qi++) {
        #pragma unroll
        for (int off = 8; off > 0; off >>= 1)
            rmax[qi] = fmaxf(rmax[qi], __shfl_xor_sync(0xffffffffu, rmax[qi], off));
    }

    if (tx == 0) {
        float part = 0.0f;
        #pragma unroll
        for (int qi = 0; qi < 4; qi++) part += rmax[qi] - qsq[qi * 16 + ty];
        atomicAdd(blksum, part);
    }
    __syncthreads();
    if (tid == 0) atomicAdd(&out[b], *blksum);
}

extern "C" void kernel_launch(void* const* d_in, const int* in_sizes, int n_in,
                              void* d_out, int out_size) {
    const float* Qg = (const float*)d_in[0];
    const float* Dg = (const float*)d_in[1];
    float* out = (float*)d_out;

    const int smem_bytes = (TQ * DPAD + TD * DPAD + TD + TQ + 4) * (int)sizeof(float);
    static int attr_set = 0;
    if (!attr_set) {
        cudaFuncSetAttribute(colbert_kernel,
                             cudaFuncAttributeMaxDynamicSharedMemorySize, smem_bytes);
        attr_set = 1;
    }

    zero_out_kernel<<<1, 128>>>(out);
    colbert_kernel<<<B_ * (LQ_ / TQ), NTHREADS, smem_bytes>>>(Qg, Dg, out);
}

// round 3
// speedup vs baseline: 5.1363x; 5.1363x over previous
#include <cuda_runtime.h>
#include <cuda_bf16.h>
#include <cstdint>

#define B_    128
#define LQ_   512
#define LD_   512
#define DIM   128
#define TM    128            // q rows per CTA
#define TN    128            // doc rows per chunk
#define NCHUNK (LD_ / TN)    // 4
#define NTHREADS 256

// ---- smem layout (bytes) ----
// bf16 tiles: 128 rows x 128 cols = 256 B/row, XOR-swizzled in 16B chunks
#define SM_QS   0
#define SM_DS   (SM_QS + TM * 256)          // 32768
#define SM_DSQ  (SM_DS + TN * 256)          // 65536
#define SM_QSQ  (SM_DSQ + TN * 4)           // 66048
#define SM_MAX  (SM_QSQ + TM * 4)           // 66560 : 128 rows x 4 warp-cols
#define SM_RED  (SM_MAX + TM * 4 * 4)       // 68608 : 8 floats
#define SMEM_TOTAL (SM_RED + 64)

__device__ __forceinline__ uint32_t smem_u32(const void* p) {
    uint32_t a;
    asm("{ .reg .u64 t; cvta.to.shared.u64 t, %1; cvt.u32.u64 %0, t; }" : "=r"(a) : "l"(p));
    return a;
}

__device__ __forceinline__ void ldmatrix_x4(uint32_t& r0, uint32_t& r1,
                                            uint32_t& r2, uint32_t& r3, uint32_t addr) {
    asm volatile("ldmatrix.sync.aligned.m8n8.x4.shared.b16 {%0,%1,%2,%3}, [%4];"
                 : "=r"(r0), "=r"(r1), "=r"(r2), "=r"(r3) : "r"(addr));
}

__device__ __forceinline__ void mma_16816(float& c0, float& c1, float& c2, float& c3,
                                          uint32_t a0, uint32_t a1, uint32_t a2, uint32_t a3,
                                          uint32_t b0, uint32_t b1) {
    asm volatile("mma.sync.aligned.m16n8k16.row.col.f32.bf16.bf16.f32 "
                 "{%0,%1,%2,%3}, {%4,%5,%6,%7}, {%8,%9}, {%0,%1,%2,%3};"
                 : "+f"(c0), "+f"(c1), "+f"(c2), "+f"(c3)
                 : "r"(a0), "r"(a1), "r"(a2), "r"(a3), "r"(b0), "r"(b1));
}

__global__ void zero_out_kernel(float* out) {
    if (threadIdx.x < B_) out[threadIdx.x] = 0.0f;
}

__global__ void __launch_bounds__(NTHREADS, 2)
colbert_mma_kernel(const float* __restrict__ Qg,
                   const float* __restrict__ Dg,
                   float* __restrict__ out) {
    extern __shared__ char smem[];
    const uint32_t sb = smem_u32(smem);
    float* dsq    = reinterpret_cast<float*>(smem + SM_DSQ);
    float* qsq    = reinterpret_cast<float*>(smem + SM_QSQ);
    float* maxbuf = reinterpret_cast<float*>(smem + SM_MAX);
    float* red    = reinterpret_cast<float*>(smem + SM_RED);

    const int tid = threadIdx.x;
    const int w = tid >> 5, l = tid & 31;
    const int wm = w >> 2;               // 0..1 : 64-row M block
    const int wn = w & 3;                // 0..3 : 32-col N block

    const int b  = blockIdx.x >> 2;      // 4 q-tiles per batch
    const int qt = blockIdx.x & 3;
    const float* Qb = Qg + ((size_t)(b * LQ_ + qt * TM)) * DIM;
    const float* Db = Dg + (size_t)b * LD_ * DIM;

    // ---- convert Q tile fp32 -> bf16 swizzled smem, fused row norms ----
    {
        char* qs = smem + SM_QS;
        #pragma unroll
        for (int j = 0; j < TM / 8; j++) {
            int row = j * 8 + w;
            float4 v = reinterpret_cast<const float4*>(Qb)[row * 32 + l];
            float s = v.x * v.x + v.y * v.y + v.z * v.z + v.w * v.w;
            #pragma unroll
            for (int o = 16; o > 0; o >>= 1) s += __shfl_xor_sync(0xffffffffu, s, o);
            if (l == 0) qsq[row] = s;
            __nv_bfloat162 p0 = __floats2bfloat162_rn(v.x, v.y);
            __nv_bfloat162 p1 = __floats2bfloat162_rn(v.z, v.w);
            uint2 pk = make_uint2(*reinterpret_cast<uint32_t*>(&p0),
                                  *reinterpret_cast<uint32_t*>(&p1));
            uint32_t addr = (uint32_t)(row * 256 + (((l >> 1) ^ (row & 7)) << 4) + ((l & 1) << 3));
            *reinterpret_cast<uint2*>(qs + addr) = pk;
        }
    }

    // ---- precompute ldmatrix lane addresses ----
    const int jj = l >> 3;               // matrix index 0..3
    const int rr = l & 7;
    // A: matrices {rows0-7/k0, rows8-15/k0, rows0-7/k1, rows8-15/k1}
    const int arow = wm * 64 + ((jj & 1) << 3) + rr;
    const int achunk_off = jj >> 1;      // +0 or +1 chunk
    const int asw = arow & 7;
    // B: matrices {n0-7/k0, n0-7/k1, n8-15/k0, n8-15/k1} within a 16-doc pair
    const int brow = wn * 32 + ((jj >> 1) << 3) + rr;
    const int bchunk_off = jj & 1;
    const int bsw = brow & 7;

    const int tg = l >> 2;               // accumulator row within 8
    const int tc = l & 3;                // accumulator col pair

    float rlo[4], rhi[4];
    #pragma unroll
    for (int mt = 0; mt < 4; mt++) { rlo[mt] = -3.402823e38f; rhi[mt] = -3.402823e38f; }

    for (int c = 0; c < NCHUNK; c++) {
        __syncthreads();  // prev epilogue done reading dsq / DS free

        // ---- convert D chunk fp32 -> bf16 swizzled smem, fused row norms ----
        {
            char* ds_ = smem + SM_DS;
            const float* src = Db + (size_t)(c * TN) * DIM;
            #pragma unroll
            for (int j = 0; j < TN / 8; j++) {
                int row = j * 8 + w;
                float4 v = reinterpret_cast<const float4*>(src)[row * 32 + l];
                float s = v.x * v.x + v.y * v.y + v.z * v.z + v.w * v.w;
                #pragma unroll
                for (int o = 16; o > 0; o >>= 1) s += __shfl_xor_sync(0xffffffffu, s, o);
                if (l == 0) dsq[row] = s;
                __nv_bfloat162 p0 = __floats2bfloat162_rn(v.x, v.y);
                __nv_bfloat162 p1 = __floats2bfloat162_rn(v.z, v.w);
                uint2 pk = make_uint2(*reinterpret_cast<uint32_t*>(&p0),
                                      *reinterpret_cast<uint32_t*>(&p1));
                uint32_t addr = (uint32_t)(row * 256 + (((l >> 1) ^ (row & 7)) << 4) + ((l & 1) << 3));
                *reinterpret_cast<uint2*>(ds_ + addr) = pk;
            }
        }
        __syncthreads();

        // ---- 128x128 tile: 4x4 m16n8k16 per warp, K=128 in 8 steps ----
        float acc[4][4][4];
        #pragma unroll
        for (int mt = 0; mt < 4; mt++)
            #pragma unroll
            for (int nt = 0; nt < 4; nt++)
                #pragma unroll
                for (int e = 0; e < 4; e++) acc[mt][nt][e] = 0.0f;

        #pragma unroll
        for (int k = 0; k < 8; k++) {
            uint32_t a[4][4];
            #pragma unroll
            for (int mt = 0; mt < 4; mt++) {
                uint32_t addr = sb + SM_QS + (uint32_t)((arow + mt * 16) * 256
                              + (((k * 2 + achunk_off) ^ asw) << 4));
                ldmatrix_x4(a[mt][0], a[mt][1], a[mt][2], a[mt][3], addr);
            }
            uint32_t bf[4][2];
            #pragma unroll
            for (int p = 0; p < 2; p++) {
                uint32_t addr = sb + SM_DS + (uint32_t)((brow + p * 16) * 256
                              + (((k * 2 + bchunk_off) ^ bsw) << 4));
                uint32_t r0, r1, r2, r3;
                ldmatrix_x4(r0, r1, r2, r3, addr);
                bf[p * 2 + 0][0] = r0; bf[p * 2 + 0][1] = r1;
                bf[p * 2 + 1][0] = r2; bf[p * 2 + 1][1] = r3;
            }
            #pragma unroll
            for (int mt = 0; mt < 4; mt++)
                #pragma unroll
                for (int nt = 0; nt < 4; nt++)
                    mma_16816(acc[mt][nt][0], acc[mt][nt][1], acc[mt][nt][2], acc[mt][nt][3],
                              a[mt][0], a[mt][1], a[mt][2], a[mt][3],
                              bf[nt][0], bf[nt][1]);
        }

        // ---- fused epilogue: neg_dist = 2*qd - d^2 ; running max ----
        #pragma unroll
        for (int nt = 0; nt < 4; nt++) {
            float2 ds2 = *reinterpret_cast<float2*>(&dsq[wn * 32 + nt * 8 + tc * 2]);
            #pragma unroll
            for (int mt = 0; mt < 4; mt++) {
                float s0 = fmaf(2.0f, acc[mt][nt][0], -ds2.x);
                float s1 = fmaf(2.0f, acc[mt][nt][1], -ds2.y);
                float s2 = fmaf(2.0f, acc[mt][nt][2], -ds2.x);
                float s3 = fmaf(2.0f, acc[mt][nt][3], -ds2.y);
                rlo[mt] = fmaxf(rlo[mt], fmaxf(s0, s1));
                rhi[mt] = fmaxf(rhi[mt], fmaxf(s2, s3));
            }
        }
    }

    // ---- cross-lane max (cols live in lane bits 0..1) ----
    #pragma unroll
    for (int mt = 0; mt < 4; mt++) {
        rlo[mt] = fmaxf(rlo[mt], __shfl_xor_sync(0xffffffffu, rlo[mt], 1));
        rlo[mt] = fmaxf(rlo[mt], __shfl_xor_sync(0xffffffffu, rlo[mt], 2));
        rhi[mt] = fmaxf(rhi[mt], __shfl_xor_sync(0xffffffffu, rhi[mt], 1));
        rhi[mt] = fmaxf(rhi[mt], __shfl_xor_sync(0xffffffffu, rhi[mt], 2));
    }
    if (tc == 0) {
        #pragma unroll
        for (int mt = 0; mt < 4; mt++) {
            maxbuf[(wm * 64 + mt * 16 + tg) * 4 + wn]     = rlo[mt];
            maxbuf[(wm * 64 + mt * 16 + 8 + tg) * 4 + wn] = rhi[mt];
        }
    }
    __syncthreads();

    // ---- final: row max across 4 warp-cols, subtract ||q||^2, block sum ----
    float val = 0.0f;
    if (tid < TM) {
        float4 m4 = *reinterpret_cast<float4*>(&maxbuf[tid * 4]);
        val = fmaxf(fmaxf(m4.x, m4.y), fmaxf(m4.z, m4.w)) - qsq[tid];
    }
    #pragma unroll
    for (int o = 16; o > 0; o >>= 1) val += __shfl_xor_sync(0xffffffffu, val, o);
    if (l == 0) red[w] = val;
    __syncthreads();
    if (tid == 0) {
        float s = 0.0f;
        #pragma unroll
        for (int i = 0; i < 8; i++) s += red[i];
        atomicAdd(&out[b], s);
    }
}

extern "C" void kernel_launch(void* const* d_in, const int* in_sizes, int n_in,
                              void* d_out, int out_size) {
    const float* Qg = (const float*)d_in[0];
    const float* Dg = (const float*)d_in[1];
    float* out = (float*)d_out;

    static int attr_set = 0;
    if (!attr_set) {
        cudaFuncSetAttribute(colbert_mma_kernel,
                             cudaFuncAttributeMaxDynamicSharedMemorySize, SMEM_TOTAL);
        attr_set = 1;
    }

    zero_out_kernel<<<1, 128>>>(out);
    colbert_mma_kernel<<<B_ * (LQ_ / TM), NTHREADS, SMEM_TOTAL>>>(Qg, Dg, out);
}